// round 4
// baseline (speedup 1.0000x reference)
#include <cuda_runtime.h>
#include <math.h>

// S2_GaussianBlur: depthwise circular 10x10 Gaussian blur, 6 x 2048 x 2048 fp32.
// out[r,c] = sum_{i,j in 0..9} K[i,j] * x[(r+i-4) & 2047, (c+j-4) & 2047]
// K = g (x) g is separable & symmetric -> two 10-tap 1D passes per tile.
// Single fused kernel: smem tile + halo, row pass -> smem, col pass -> gmem.

#define N        2048
#define MASK     2047
#define KS       10
#define RAD      4          // taps cover offsets -4 .. +5
#define TX       64
#define TY       64
#define HX       (TX + KS - 1)   // 73
#define HY       (TY + KS - 1)   // 73
#define NTHREADS 256

__constant__ float c_mtf[6] = {0.38f, 0.34f, 0.34f, 0.26f, 0.22f, 0.23f};

__global__ __launch_bounds__(NTHREADS, 5)
void s2_gaussian_blur_kernel(const float* __restrict__ x, float* __restrict__ out)
{
    __shared__ float s_in[HY][HX];     // 73 x 73 input tile (with halo)
    __shared__ float s_mid[HY][TX];    // row-filtered intermediate
    __shared__ float s_h[KS];          // normalized 1D gaussian taps

    const int ch  = blockIdx.z;
    const int tid = threadIdx.x;

    // --- per-block tap computation (fp64, once; symmetric so flip is a no-op) ---
    if (tid == 0) {
        double mtf   = (double)c_mtf[ch];
        double sigma = 2.0 * sqrt(-2.0 * log(mtf) / (M_PI * M_PI)); // scale=2
        double g[KS];
        double s = 0.0;
        #pragma unroll
        for (int t = 0; t < KS; t++) {
            double coord = (double)t - 4.5;               // -4.5 .. 4.5
            g[t] = exp(-coord * coord / (2.0 * sigma * sigma));
            s += g[t];
        }
        #pragma unroll
        for (int t = 0; t < KS; t++) s_h[t] = (float)(g[t] / s);
    }

    // --- load 73x73 input tile with circular wrap (runs concurrently with tap calc) ---
    const int row0 = blockIdx.y * TY - RAD;
    const int col0 = blockIdx.x * TX - RAD;
    const float* __restrict__ xc = x + (size_t)ch * N * N;

    for (int i = tid; i < HY * HX; i += NTHREADS) {
        int ly = i / HX;
        int lx = i - ly * HX;
        int r = (row0 + ly) & MASK;
        int c = (col0 + lx) & MASK;
        s_in[ly][lx] = xc[(size_t)r * N + c];
    }
    __syncthreads();   // covers both s_h and s_in

    float h[KS];
    #pragma unroll
    for (int t = 0; t < KS; t++) h[t] = s_h[t];

    // --- row pass: 73 rows x 64 cols ---
    for (int i = tid; i < HY * TX; i += NTHREADS) {
        int ly = i >> 6;            // / TX
        int lx = i & (TX - 1);
        float acc = 0.0f;
        #pragma unroll
        for (int t = 0; t < KS; t++) acc += h[t] * s_in[ly][lx + t];
        s_mid[ly][lx] = acc;
    }
    __syncthreads();

    // --- column pass + coalesced store: 64 x 64 outputs ---
    float* __restrict__ oc = out + (size_t)ch * N * N;
    const int orow0 = blockIdx.y * TY;
    const int ocol0 = blockIdx.x * TX;

    for (int i = tid; i < TY * TX; i += NTHREADS) {
        int ty = i >> 6;
        int tx = i & (TX - 1);
        float acc = 0.0f;
        #pragma unroll
        for (int t = 0; t < KS; t++) acc += h[t] * s_mid[ty + t][tx];
        oc[(size_t)(orow0 + ty) * N + (ocol0 + tx)] = acc;
    }
}

extern "C" void kernel_launch(void* const* d_in, const int* in_sizes, int n_in,
                              void* d_out, int out_size)
{
    const float* x = (const float*)d_in[0];   // (1, 6, 2048, 2048) fp32
    float* out = (float*)d_out;               // same shape

    dim3 grid(N / TX, N / TY, 6);             // 32 x 32 x 6 = 6144 blocks
    s2_gaussian_blur_kernel<<<grid, NTHREADS>>>(x, out);
}

// round 6
// speedup vs baseline: 2.9569x; 2.9569x over previous
#include <cuda_runtime.h>
#include <math.h>

// S2_GaussianBlur: depthwise circular 10x10 Gaussian blur, 6 x 2048 x 2048 fp32.
// out[r,c] = sum_{t,u} h[t]h[u] * x[(r+t-4)&2047, (c+u-4)&2047]  (separable, symmetric)
//
// Fully vectorized separable design:
//   row pass : gmem float4 loads (halo overlap served by L1) -> s_mid (float4 smem)
//   col pass : sliding-window over s_mid, 13 LDS.128 -> 4 float4 outputs -> STG.128
// One __syncthreads total. All indexing is shift/mask (N = 2^11, lanes 4-aligned).

#define N     2048
#define MASK  2047
#define N4    (N / 4)
#define KS    10
#define RAD   4
#define TX    64            // 16 float4 groups
#define TY    64
#define HY    (TY + KS - 1) // 73
#define NT    256

__constant__ float c_mtf[6] = {0.38f, 0.34f, 0.34f, 0.26f, 0.22f, 0.23f};

__global__ __launch_bounds__(NT, 5)
void s2_gaussian_blur_kernel(const float* __restrict__ x, float* __restrict__ out)
{
    __shared__ float4 s_mid[HY * 16];   // 73 rows x 16 float4 = 18688 B

    const int tid = threadIdx.x;
    const int ch  = blockIdx.z;

    // --- per-thread taps (fp32; normalized 1D gaussian, symmetric -> no flip) ---
    float h[KS];
    {
        float mtf  = c_mtf[ch];
        float sig2 = 4.0f * (-2.0f * logf(mtf) / (float)(M_PI * M_PI)); // (scale*sigma)^2
        float inv  = -1.0f / (2.0f * sig2);
        float sum  = 0.0f;
        #pragma unroll
        for (int t = 0; t < KS; ++t) {
            float d = (float)t - 4.5f;
            h[t] = expf(d * d * inv);
            sum += h[t];
        }
        float rs = 1.0f / sum;
        #pragma unroll
        for (int t = 0; t < KS; ++t) h[t] *= rs;
    }

    const float4* __restrict__ x4 =
        reinterpret_cast<const float4*>(x) + (size_t)ch * N * N4;
    const int row0 = blockIdx.y * TY - RAD;
    const int col0 = blockIdx.x * TX;

    // --- row pass: 73 rows x 16 groups, gmem -> registers -> s_mid ---
    #pragma unroll
    for (int it = 0; it < (HY * 16 + NT - 1) / NT; ++it) {
        int idx = tid + it * NT;
        if (idx < HY * 16) {
            int ly = idx >> 4;
            int g  = idx & 15;
            const size_t rbase = (size_t)((row0 + ly) & MASK) * N4;
            float a[16];
            #pragma unroll
            for (int k = 0; k < 4; ++k) {
                int c = (col0 + g * 4 - RAD + 4 * k) & MASK;  // 4-aligned, wrap-safe
                float4 v = x4[rbase + (c >> 2)];
                a[4 * k + 0] = v.x; a[4 * k + 1] = v.y;
                a[4 * k + 2] = v.z; a[4 * k + 3] = v.w;
            }
            float4 m = make_float4(0.f, 0.f, 0.f, 0.f);
            #pragma unroll
            for (int t = 0; t < KS; ++t) {
                m.x = fmaf(h[t], a[t + 0], m.x);
                m.y = fmaf(h[t], a[t + 1], m.y);
                m.z = fmaf(h[t], a[t + 2], m.z);
                m.w = fmaf(h[t], a[t + 3], m.w);
            }
            s_mid[idx] = m;
        }
    }
    __syncthreads();

    // --- col pass: sliding window, 4 output rows x 1 float4 per thread ---
    const int g  = tid & 15;
    const int rb = (tid >> 4) * 4;          // 0..60
    float4 acc[4] = { make_float4(0,0,0,0), make_float4(0,0,0,0),
                      make_float4(0,0,0,0), make_float4(0,0,0,0) };
    #pragma unroll
    for (int k = 0; k < KS + 3; ++k) {      // 13 window rows
        float4 v = s_mid[(rb + k) * 16 + g];
        #pragma unroll
        for (int j = 0; j < 4; ++j) {
            int t = k - j;
            if (t >= 0 && t < KS) {
                acc[j].x = fmaf(h[t], v.x, acc[j].x);
                acc[j].y = fmaf(h[t], v.y, acc[j].y);
                acc[j].z = fmaf(h[t], v.z, acc[j].z);
                acc[j].w = fmaf(h[t], v.w, acc[j].w);
            }
        }
    }

    float4* __restrict__ o4 =
        reinterpret_cast<float4*>(out) + (size_t)ch * N * N4;
    const int R0 = blockIdx.y * TY;
    const int oc = (col0 >> 2) + g;
    #pragma unroll
    for (int j = 0; j < 4; ++j)
        o4[(size_t)(R0 + rb + j) * N4 + oc] = acc[j];
}

extern "C" void kernel_launch(void* const* d_in, const int* in_sizes, int n_in,
                              void* d_out, int out_size)
{
    const float* x = (const float*)d_in[0];   // (1, 6, 2048, 2048) fp32
    float* out = (float*)d_out;

    dim3 grid(N / TX, N / TY, 6);             // 32 x 32 x 6
    s2_gaussian_blur_kernel<<<grid, NT>>>(x, out);
}

// round 8
// speedup vs baseline: 3.3030x; 1.1170x over previous
#include <cuda_runtime.h>
#include <math.h>

// S2_GaussianBlur: depthwise circular 10x10 Gaussian blur, 6 x 2048 x 2048 fp32.
// out[r,c] = sum_{t,u} h[t]h[u] * x[(r+t-4)&2047, (c+u-4)&2047]  (separable, symmetric)
//
// Tile 64 wide x 128 tall. Row pass: 5 LDG.128 -> 8 outputs (2 STS.128) per work
// item. Col pass: 17 LDS.128 sliding window -> 8 float4 outputs per thread.
// One __syncthreads. All indexing shift/mask (N = 2^11, lanes 4-aligned).

#define N     2048
#define MASK  2047
#define N4    (N / 4)
#define KS    10
#define RAD   4
#define TX    64             // 16 float4 lanes
#define TY    128
#define HY    (TY + KS - 1)  // 137
#define NT    256
#define ROWITEMS (HY * 8)    // 8 work groups of 8 cols per mid row = 1096

__constant__ float c_mtf[6] = {0.38f, 0.34f, 0.34f, 0.26f, 0.22f, 0.23f};

__global__ __launch_bounds__(NT, 4)
void s2_gaussian_blur_kernel(const float* __restrict__ x, float* __restrict__ out)
{
    __shared__ float4 s_mid[HY * 16];   // 137 rows x 16 float4 = 35072 B

    const int tid = threadIdx.x;
    const int ch  = blockIdx.z;

    // --- per-thread taps (fp32; normalized 1D gaussian, symmetric -> no flip) ---
    float h[KS];
    {
        float mtf  = c_mtf[ch];
        float sig2 = 4.0f * (-2.0f * logf(mtf) / (float)(M_PI * M_PI)); // (scale*sigma)^2
        float inv  = -1.0f / (2.0f * sig2);
        float sum  = 0.0f;
        #pragma unroll
        for (int t = 0; t < KS; ++t) {
            float d = (float)t - 4.5f;
            h[t] = expf(d * d * inv);
            sum += h[t];
        }
        float rs = 1.0f / sum;
        #pragma unroll
        for (int t = 0; t < KS; ++t) h[t] *= rs;
    }

    const float4* __restrict__ x4 =
        reinterpret_cast<const float4*>(x) + (size_t)ch * N * N4;
    const int row0 = blockIdx.y * TY - RAD;
    const int col0 = blockIdx.x * TX;

    // --- row pass: 137 rows x 8 groups of 8 cols; 5 LDG.128 -> 8 outputs ---
    #pragma unroll
    for (int it = 0; it < (ROWITEMS + NT - 1) / NT; ++it) {
        int idx = tid + it * NT;
        if (idx < ROWITEMS) {
            int ly = idx >> 3;           // mid row 0..136
            int g  = idx & 7;            // 8-col group
            const size_t rbase = (size_t)((row0 + ly) & MASK) * N4;
            float a[20];
            #pragma unroll
            for (int k = 0; k < 5; ++k) {
                int c = (col0 + g * 8 - RAD + 4 * k) & MASK;  // 4-aligned, wrap-safe
                float4 v = x4[rbase + (c >> 2)];
                a[4 * k + 0] = v.x; a[4 * k + 1] = v.y;
                a[4 * k + 2] = v.z; a[4 * k + 3] = v.w;
            }
            float4 m0 = make_float4(0.f, 0.f, 0.f, 0.f);
            float4 m1 = make_float4(0.f, 0.f, 0.f, 0.f);
            #pragma unroll
            for (int t = 0; t < KS; ++t) {
                m0.x = fmaf(h[t], a[t + 0], m0.x);
                m0.y = fmaf(h[t], a[t + 1], m0.y);
                m0.z = fmaf(h[t], a[t + 2], m0.z);
                m0.w = fmaf(h[t], a[t + 3], m0.w);
                m1.x = fmaf(h[t], a[t + 4], m1.x);
                m1.y = fmaf(h[t], a[t + 5], m1.y);
                m1.z = fmaf(h[t], a[t + 6], m1.z);
                m1.w = fmaf(h[t], a[t + 7], m1.w);
            }
            s_mid[ly * 16 + 2 * g + 0] = m0;
            s_mid[ly * 16 + 2 * g + 1] = m1;
        }
    }
    __syncthreads();

    // --- col pass: sliding window, 8 output rows x 1 float4 per thread ---
    const int g  = tid & 15;             // float4 column
    const int rb = (tid >> 4) * 8;       // output row block 0..120
    float4 acc[8];
    #pragma unroll
    for (int j = 0; j < 8; ++j) acc[j] = make_float4(0.f, 0.f, 0.f, 0.f);

    #pragma unroll
    for (int k = 0; k < KS + 7; ++k) {   // 17 window rows
        float4 v = s_mid[(rb + k) * 16 + g];
        #pragma unroll
        for (int j = 0; j < 8; ++j) {
            int t = k - j;
            if (t >= 0 && t < KS) {
                acc[j].x = fmaf(h[t], v.x, acc[j].x);
                acc[j].y = fmaf(h[t], v.y, acc[j].y);
                acc[j].z = fmaf(h[t], v.z, acc[j].z);
                acc[j].w = fmaf(h[t], v.w, acc[j].w);
            }
        }
    }

    float4* __restrict__ o4 =
        reinterpret_cast<float4*>(out) + (size_t)ch * N * N4;
    const int R0 = blockIdx.y * TY;
    const int oc = (col0 >> 2) + g;
    #pragma unroll
    for (int j = 0; j < 8; ++j)
        o4[(size_t)(R0 + rb + j) * N4 + oc] = acc[j];
}

extern "C" void kernel_launch(void* const* d_in, const int* in_sizes, int n_in,
                              void* d_out, int out_size)
{
    const float* x = (const float*)d_in[0];   // (1, 6, 2048, 2048) fp32
    float* out = (float*)d_out;

    dim3 grid(N / TX, N / TY, 6);             // 32 x 16 x 6
    s2_gaussian_blur_kernel<<<grid, NT>>>(x, out);
}

// round 9
// speedup vs baseline: 3.4140x; 1.0336x over previous
#include <cuda_runtime.h>
#include <cuda_fp16.h>
#include <math.h>

// S2_GaussianBlur: depthwise circular 10x10 Gaussian blur, 6 x 2048 x 2048 fp32.
// out[r,c] = sum_{t,u} h[t]h[u] * x[(r+t-4)&2047, (c+u-4)&2047]  (separable, symmetric)
//
// Tile 64 wide x 128 tall.
//   row pass : 7 LDG.128 -> 16 fp32 mid values -> packed fp16 -> 2 STS.128
//   col pass : 17 LDS.64 (half2 pairs) sliding window -> 8 float4 outputs -> STG.128
// Intermediate stored as fp16 (halves smem traffic; accumulation stays fp32).
// One __syncthreads. All indexing shift/mask (N = 2^11, lanes 4-aligned).

#define N     2048
#define MASK  2047
#define N4    (N / 4)
#define KS    10
#define RAD   4
#define TX    64             // 16 float4 lanes
#define TY    128
#define HY    (TY + KS - 1)  // 137
#define NT    256
#define ROWITEMS (HY * 4)    // 4 groups of 16 cols per mid row = 548

__constant__ float c_mtf[6] = {0.38f, 0.34f, 0.34f, 0.26f, 0.22f, 0.23f};

__global__ __launch_bounds__(NT, 4)
void s2_gaussian_blur_kernel(const float* __restrict__ x, float* __restrict__ out)
{
    // one mid row = 64 halves = 128 B = 16 uint2 (= 8 uint4)
    __shared__ uint2 s_mid[HY * 16];    // 17536 B

    const int tid = threadIdx.x;
    const int ch  = blockIdx.z;

    // --- per-thread taps (fp32; normalized 1D gaussian, symmetric -> no flip) ---
    float h[KS];
    {
        float mtf  = c_mtf[ch];
        float sig2 = 4.0f * (-2.0f * logf(mtf) / (float)(M_PI * M_PI)); // (scale*sigma)^2
        float inv  = -1.0f / (2.0f * sig2);
        float sum  = 0.0f;
        #pragma unroll
        for (int t = 0; t < KS; ++t) {
            float d = (float)t - 4.5f;
            h[t] = expf(d * d * inv);
            sum += h[t];
        }
        float rs = 1.0f / sum;
        #pragma unroll
        for (int t = 0; t < KS; ++t) h[t] *= rs;
    }

    const float4* __restrict__ x4 =
        reinterpret_cast<const float4*>(x) + (size_t)ch * N * N4;
    const int row0 = blockIdx.y * TY - RAD;
    const int col0 = blockIdx.x * TX;

    // --- row pass: 137 rows x 4 groups of 16 cols; 7 LDG.128 -> 16 mid -> fp16 ---
    uint4* __restrict__ s_mid4 = reinterpret_cast<uint4*>(s_mid);
    #pragma unroll
    for (int it = 0; it < (ROWITEMS + NT - 1) / NT; ++it) {
        int idx = tid + it * NT;
        if (idx < ROWITEMS) {
            int ly = idx >> 2;           // mid row 0..136
            int g  = idx & 3;            // 16-col group
            const size_t rbase = (size_t)((row0 + ly) & MASK) * N4;
            float a[28];
            #pragma unroll
            for (int k = 0; k < 7; ++k) {
                int c = (col0 + g * 16 - RAD + 4 * k) & MASK;  // 4-aligned, wrap-safe
                float4 v = x4[rbase + (c >> 2)];
                a[4 * k + 0] = v.x; a[4 * k + 1] = v.y;
                a[4 * k + 2] = v.z; a[4 * k + 3] = v.w;
            }
            float m[16];
            #pragma unroll
            for (int o = 0; o < 16; ++o) m[o] = 0.0f;
            #pragma unroll
            for (int t = 0; t < KS; ++t) {
                #pragma unroll
                for (int o = 0; o < 16; ++o)
                    m[o] = fmaf(h[t], a[o + t], m[o]);
            }
            union { uint4 u[2]; __half2 hh[8]; } P;
            #pragma unroll
            for (int j = 0; j < 8; ++j)
                P.hh[j] = __floats2half2_rn(m[2 * j], m[2 * j + 1]);
            s_mid4[ly * 8 + g * 2 + 0] = P.u[0];
            s_mid4[ly * 8 + g * 2 + 1] = P.u[1];
        }
    }
    __syncthreads();

    // --- col pass: sliding window over fp16 mid, 8 output rows x 1 float4/thread ---
    const int g  = tid & 15;             // float4 column group
    const int rb = (tid >> 4) * 8;       // output row block 0..120
    float4 acc[8];
    #pragma unroll
    for (int j = 0; j < 8; ++j) acc[j] = make_float4(0.f, 0.f, 0.f, 0.f);

    #pragma unroll
    for (int k = 0; k < KS + 7; ++k) {   // 17 window rows
        uint2 w = s_mid[(rb + k) * 16 + g];          // 4 halves = cols 4g..4g+3
        __half2 h0 = *reinterpret_cast<__half2*>(&w.x);
        __half2 h1 = *reinterpret_cast<__half2*>(&w.y);
        float2 f0 = __half22float2(h0);
        float2 f1 = __half22float2(h1);
        #pragma unroll
        for (int j = 0; j < 8; ++j) {
            int t = k - j;
            if (t >= 0 && t < KS) {
                acc[j].x = fmaf(h[t], f0.x, acc[j].x);
                acc[j].y = fmaf(h[t], f0.y, acc[j].y);
                acc[j].z = fmaf(h[t], f1.x, acc[j].z);
                acc[j].w = fmaf(h[t], f1.y, acc[j].w);
            }
        }
    }

    float4* __restrict__ o4 =
        reinterpret_cast<float4*>(out) + (size_t)ch * N * N4;
    const int R0 = blockIdx.y * TY;
    const int oc = (col0 >> 2) + g;
    #pragma unroll
    for (int j = 0; j < 8; ++j)
        o4[(size_t)(R0 + rb + j) * N4 + oc] = acc[j];
}

extern "C" void kernel_launch(void* const* d_in, const int* in_sizes, int n_in,
                              void* d_out, int out_size)
{
    const float* x = (const float*)d_in[0];   // (1, 6, 2048, 2048) fp32
    float* out = (float*)d_out;

    dim3 grid(N / TX, N / TY, 6);             // 32 x 16 x 6
    s2_gaussian_blur_kernel<<<grid, NT>>>(x, out);
}

// round 11
// speedup vs baseline: 3.4163x; 1.0007x over previous
#include <cuda_runtime.h>
#include <cuda_fp16.h>
#include <math.h>

// S2_GaussianBlur: depthwise circular 10x10 Gaussian blur, 6 x 2048 x 2048 fp32.
// out[r,c] = sum_{t,u} h[t]h[u] * x[(r+t-4)&2047, (c+u-4)&2047]  (separable, symmetric)
//
// Tile 64 wide x 128 tall.
//   row pass : 7 LDG.128 -> 16 fp32 mid values -> packed fp16 -> 2 STS.128
//   col pass : 17 LDS.64 sliding window; accumulation in packed fma.rn.f32x2
//              (Blackwell FFMA2: 2 fp32 FMAs per instruction) -> STG.128
// Intermediate stored fp16 (storage only; all accumulation fp32).
// One __syncthreads. All indexing shift/mask (N = 2^11, lanes 4-aligned).

#define N     2048
#define MASK  2047
#define N4    (N / 4)
#define KS    10
#define RAD   4
#define TX    64             // 16 float4 lanes
#define TY    128
#define HY    (TY + KS - 1)  // 137
#define NT    256
#define ROWITEMS (HY * 4)    // 4 groups of 16 cols per mid row = 548

typedef unsigned long long u64;

__device__ __forceinline__ u64 pack2(float lo, float hi) {
    u64 r;
    asm("mov.b64 %0, {%1, %2};" : "=l"(r) : "f"(lo), "f"(hi));
    return r;
}
__device__ __forceinline__ u64 fma2(u64 a, u64 b, u64 c) {
    u64 d;
    asm("fma.rn.f32x2 %0, %1, %2, %3;" : "=l"(d) : "l"(a), "l"(b), "l"(c));
    return d;
}
__device__ __forceinline__ float2 unpack2(u64 v) {
    float lo, hi;
    asm("mov.b64 {%0, %1}, %2;" : "=f"(lo), "=f"(hi) : "l"(v));
    return make_float2(lo, hi);
}

__constant__ float c_mtf[6] = {0.38f, 0.34f, 0.34f, 0.26f, 0.22f, 0.23f};

__global__ __launch_bounds__(NT, 4)
void s2_gaussian_blur_kernel(const float* __restrict__ x, float* __restrict__ out)
{
    // one mid row = 64 halves = 128 B = 16 uint2 (= 8 uint4)
    __shared__ uint2 s_mid[HY * 16];    // 17536 B

    const int tid = threadIdx.x;
    const int ch  = blockIdx.z;

    // --- per-thread taps (fp32; normalized 1D gaussian, symmetric -> no flip) ---
    float h[KS];
    {
        float mtf  = c_mtf[ch];
        float sig2 = 4.0f * (-2.0f * logf(mtf) / (float)(M_PI * M_PI)); // (scale*sigma)^2
        float inv  = -1.0f / (2.0f * sig2);
        float sum  = 0.0f;
        #pragma unroll
        for (int t = 0; t < KS; ++t) {
            float d = (float)t - 4.5f;
            h[t] = expf(d * d * inv);
            sum += h[t];
        }
        float rs = 1.0f / sum;
        #pragma unroll
        for (int t = 0; t < KS; ++t) h[t] *= rs;
    }

    const float4* __restrict__ x4 =
        reinterpret_cast<const float4*>(x) + (size_t)ch * N * N4;
    const int row0 = blockIdx.y * TY - RAD;
    const int col0 = blockIdx.x * TX;

    // --- row pass: 137 rows x 4 groups of 16 cols; 7 LDG.128 -> 16 mid -> fp16 ---
    uint4* __restrict__ s_mid4 = reinterpret_cast<uint4*>(s_mid);
    #pragma unroll
    for (int it = 0; it < (ROWITEMS + NT - 1) / NT; ++it) {
        int idx = tid + it * NT;
        if (idx < ROWITEMS) {
            int ly = idx >> 2;           // mid row 0..136
            int g  = idx & 3;            // 16-col group
            const size_t rbase = (size_t)((row0 + ly) & MASK) * N4;
            float a[28];
            #pragma unroll
            for (int k = 0; k < 7; ++k) {
                int c = (col0 + g * 16 - RAD + 4 * k) & MASK;  // 4-aligned, wrap-safe
                float4 v = x4[rbase + (c >> 2)];
                a[4 * k + 0] = v.x; a[4 * k + 1] = v.y;
                a[4 * k + 2] = v.z; a[4 * k + 3] = v.w;
            }
            float m[16];
            #pragma unroll
            for (int o = 0; o < 16; ++o) m[o] = 0.0f;
            #pragma unroll
            for (int t = 0; t < KS; ++t) {
                #pragma unroll
                for (int o = 0; o < 16; ++o)
                    m[o] = fmaf(h[t], a[o + t], m[o]);
            }
            union { uint4 u[2]; __half2 hh[8]; } P;
            #pragma unroll
            for (int j = 0; j < 8; ++j)
                P.hh[j] = __floats2half2_rn(m[2 * j], m[2 * j + 1]);
            s_mid4[ly * 8 + g * 2 + 0] = P.u[0];
            s_mid4[ly * 8 + g * 2 + 1] = P.u[1];
        }
    }
    __syncthreads();

    // --- col pass: sliding window over fp16 mid, packed f32x2 accumulation ---
    // broadcast-packed taps (h[t], h[t]) for f32x2 multiplier
    u64 hh[KS];
    #pragma unroll
    for (int t = 0; t < KS; ++t) hh[t] = pack2(h[t], h[t]);

    const int g  = tid & 15;             // float4 column group
    const int rb = (tid >> 4) * 8;       // output row block 0..120
    u64 accA[8], accB[8];                // accA = cols (0,1), accB = cols (2,3)
    #pragma unroll
    for (int j = 0; j < 8; ++j) { accA[j] = 0ull; accB[j] = 0ull; }

    #pragma unroll
    for (int k = 0; k < KS + 7; ++k) {   // 17 window rows
        uint2 w = s_mid[(rb + k) * 16 + g];          // 4 halves = cols 4g..4g+3
        float2 f0 = __half22float2(*reinterpret_cast<__half2*>(&w.x));
        float2 f1 = __half22float2(*reinterpret_cast<__half2*>(&w.y));
        u64 b0 = pack2(f0.x, f0.y);
        u64 b1 = pack2(f1.x, f1.y);
        #pragma unroll
        for (int j = 0; j < 8; ++j) {
            int t = k - j;
            if (t >= 0 && t < KS) {
                accA[j] = fma2(hh[t], b0, accA[j]);
                accB[j] = fma2(hh[t], b1, accB[j]);
            }
        }
    }

    float4* __restrict__ o4 =
        reinterpret_cast<float4*>(out) + (size_t)ch * N * N4;
    const int R0 = blockIdx.y * TY;
    const int oc = (col0 >> 2) + g;
    #pragma unroll
    for (int j = 0; j < 8; ++j) {
        float2 lo = unpack2(accA[j]);
        float2 hi = unpack2(accB[j]);
        o4[(size_t)(R0 + rb + j) * N4 + oc] = make_float4(lo.x, lo.y, hi.x, hi.y);
    }
}

extern "C" void kernel_launch(void* const* d_in, const int* in_sizes, int n_in,
                              void* d_out, int out_size)
{
    const float* x = (const float*)d_in[0];   // (1, 6, 2048, 2048) fp32
    float* out = (float*)d_out;

    dim3 grid(N / TX, N / TY, 6);             // 32 x 16 x 6
    s2_gaussian_blur_kernel<<<grid, NT>>>(x, out);
}